// round 1
// baseline (speedup 1.0000x reference)
#include <cuda_runtime.h>
#include <math.h>

#define BATCH 4
#define SEQ 2048
#define IN_DIM 512
#define DMODEL 256
#define NHEAD 4
#define HDIM 64
#define NLAYER 4
#define FFDIM 2048
#define NTOK (BATCH * SEQ)   // 8192

// ---------------- scratch (device globals, no allocation) ----------------
__device__ float g_h[NTOK * DMODEL];      // activations
__device__ float g_qkv[NTOK * 3 * DMODEL];
__device__ float g_ctx[NTOK * DMODEL];
__device__ float g_sa[NTOK * DMODEL];
__device__ float g_ff[NTOK * FFDIM];
__device__ float g_pe[SEQ * DMODEL];

// ---------------- positional encoding ----------------
__global__ void pe_kernel() {
    int idx = blockIdx.x * blockDim.x + threadIdx.x;
    if (idx >= SEQ * DMODEL) return;
    int s = idx / DMODEL;
    int d = idx % DMODEL;
    int i = d >> 1;
    float freq = __expf(-(float)(2 * i) * (9.210340371976184f / 256.0f));
    float v = (float)s * freq;
    g_pe[idx] = (d & 1) ? cosf(v) : sinf(v);
}

// ---------------- generic NT GEMM: C[m,n] = sum_k A[m,k]*B[n,k] + bias[n] ----------------
// EPI: 0 = bias only, 1 = bias + relu, 2 = bias + positional encoding (N == DMODEL)
#define BM 128
#define BN 128
#define BK 8
#define TM 8
#define TN 8

template <int EPI>
__global__ void __launch_bounds__(256) gemm_nt(const float* __restrict__ A,
                                               const float* __restrict__ B,
                                               const float* __restrict__ bias,
                                               float* __restrict__ C,
                                               int M, int N, int K) {
    __shared__ float As[BK][BM + 4];
    __shared__ float Bs[BK][BN + 4];

    int tid = threadIdx.x;
    int bm = blockIdx.y * BM;
    int bn = blockIdx.x * BN;

    int lrow = tid >> 1;            // 0..127
    int lcol = (tid & 1) * 4;       // 0 or 4

    int tx = tid & 15;
    int ty = tid >> 4;

    float acc[TM][TN];
#pragma unroll
    for (int i = 0; i < TM; i++)
#pragma unroll
        for (int j = 0; j < TN; j++) acc[i][j] = 0.0f;

    const float* aptr = A + (size_t)(bm + lrow) * K + lcol;
    const float* bptr = B + (size_t)(bn + lrow) * K + lcol;

    for (int k0 = 0; k0 < K; k0 += BK) {
        float4 a4 = *(const float4*)(aptr + k0);
        float4 b4 = *(const float4*)(bptr + k0);
        As[lcol + 0][lrow] = a4.x;
        As[lcol + 1][lrow] = a4.y;
        As[lcol + 2][lrow] = a4.z;
        As[lcol + 3][lrow] = a4.w;
        Bs[lcol + 0][lrow] = b4.x;
        Bs[lcol + 1][lrow] = b4.y;
        Bs[lcol + 2][lrow] = b4.z;
        Bs[lcol + 3][lrow] = b4.w;
        __syncthreads();

#pragma unroll
        for (int kk = 0; kk < BK; kk++) {
            float ar[TM], br[TN];
#pragma unroll
            for (int i = 0; i < TM; i++) ar[i] = As[kk][ty * TM + i];
#pragma unroll
            for (int j = 0; j < TN; j++) br[j] = Bs[kk][tx * TN + j];
#pragma unroll
            for (int i = 0; i < TM; i++)
#pragma unroll
                for (int j = 0; j < TN; j++) acc[i][j] += ar[i] * br[j];
        }
        __syncthreads();
    }

#pragma unroll
    for (int i = 0; i < TM; i++) {
        int row = bm + ty * TM + i;
#pragma unroll
        for (int j = 0; j < TN; j++) {
            int col = bn + tx * TN + j;
            float v = acc[i][j] + bias[col];
            if (EPI == 1) v = fmaxf(v, 0.0f);
            if (EPI == 2) v += g_pe[(row & (SEQ - 1)) * DMODEL + col];
            C[(size_t)row * N + col] = v;
        }
    }
}

// ---------------- flash attention ----------------
// grid: (B*H, SEQ/128), block: 128 threads, 1 query per thread
#define KT 32
__global__ void __launch_bounds__(128) flash_kernel(const float* __restrict__ qkv,
                                                    float* __restrict__ ctx_out) {
    int bh = blockIdx.x;            // 0..15
    int qt = blockIdx.y;            // 0..15
    int b = bh >> 2;
    int hh = bh & 3;
    int tid = threadIdx.x;

    int q_token = b * SEQ + qt * 128 + tid;
    const float scale = 0.125f;     // 1/sqrt(64)

    __shared__ float4 sk[KT * 16];
    __shared__ float4 sv[KT * 16];
    __shared__ float ss[KT * 128];

    float4 q[16];
    const float4* qptr = (const float4*)(qkv + (size_t)q_token * 768 + hh * HDIM);
#pragma unroll
    for (int f = 0; f < 16; f++) {
        float4 t = qptr[f];
        q[f] = make_float4(t.x * scale, t.y * scale, t.z * scale, t.w * scale);
    }

    float m = -1e30f, l = 0.0f;
    float4 ctx[16];
#pragma unroll
    for (int f = 0; f < 16; f++) ctx[f] = make_float4(0.f, 0.f, 0.f, 0.f);

    for (int kt = 0; kt < SEQ / KT; kt++) {
        int kbase = b * SEQ + kt * KT;
        // load K/V tile: KT*16 = 512 float4 each; 128 threads x 4
#pragma unroll
        for (int i = 0; i < 4; i++) {
            int idx = i * 128 + tid;
            int key = idx >> 4;
            int f = idx & 15;
            const float* row = qkv + (size_t)(kbase + key) * 768 + DMODEL + hh * HDIM;
            sk[idx] = ((const float4*)row)[f];
            sv[idx] = ((const float4*)(row + DMODEL))[f];
        }
        __syncthreads();

        float tmax = -1e30f;
#pragma unroll 4
        for (int j = 0; j < KT; j++) {
            float s = 0.0f;
#pragma unroll
            for (int f = 0; f < 16; f++) {
                float4 kv = sk[j * 16 + f];
                s += q[f].x * kv.x + q[f].y * kv.y + q[f].z * kv.z + q[f].w * kv.w;
            }
            ss[j * 128 + tid] = s;
            tmax = fmaxf(tmax, s);
        }

        float nm = fmaxf(m, tmax);
        float corr = __expf(m - nm);
        l *= corr;
#pragma unroll
        for (int f = 0; f < 16; f++) {
            ctx[f].x *= corr; ctx[f].y *= corr; ctx[f].z *= corr; ctx[f].w *= corr;
        }

#pragma unroll 4
        for (int j = 0; j < KT; j++) {
            float p = __expf(ss[j * 128 + tid] - nm);
            l += p;
#pragma unroll
            for (int f = 0; f < 16; f++) {
                float4 vv = sv[j * 16 + f];
                ctx[f].x += p * vv.x; ctx[f].y += p * vv.y;
                ctx[f].z += p * vv.z; ctx[f].w += p * vv.w;
            }
        }
        m = nm;
        __syncthreads();
    }

    float inv = 1.0f / l;
    float4* out = (float4*)(ctx_out + (size_t)q_token * DMODEL + hh * HDIM);
#pragma unroll
    for (int f = 0; f < 16; f++)
        out[f] = make_float4(ctx[f].x * inv, ctx[f].y * inv, ctx[f].z * inv, ctx[f].w * inv);
}

// ---------------- residual + layernorm (in-place into g_h) ----------------
__global__ void __launch_bounds__(256) ln_kernel(const float* __restrict__ res,
                                                 const float* __restrict__ w,
                                                 const float* __restrict__ b) {
    int t = blockIdx.x;
    int i = threadIdx.x;
    size_t off = (size_t)t * DMODEL + i;
    float x = g_h[off] + res[off];

    float s = x, s2 = x * x;
#pragma unroll
    for (int o = 16; o > 0; o >>= 1) {
        s  += __shfl_xor_sync(0xffffffffu, s, o);
        s2 += __shfl_xor_sync(0xffffffffu, s2, o);
    }
    __shared__ float red[2][8];
    int warp = i >> 5, lane = i & 31;
    if (lane == 0) { red[0][warp] = s; red[1][warp] = s2; }
    __syncthreads();
    if (warp == 0) {
        float a = (lane < 8) ? red[0][lane] : 0.0f;
        float a2 = (lane < 8) ? red[1][lane] : 0.0f;
#pragma unroll
        for (int o = 4; o > 0; o >>= 1) {
            a  += __shfl_xor_sync(0xffffffffu, a, o);
            a2 += __shfl_xor_sync(0xffffffffu, a2, o);
        }
        if (lane == 0) { red[0][0] = a; red[1][0] = a2; }
    }
    __syncthreads();
    float mu = red[0][0] * (1.0f / DMODEL);
    float var = red[1][0] * (1.0f / DMODEL) - mu * mu;
    float y = (x - mu) * rsqrtf(var + 1e-5f) * w[i] + b[i];
    g_h[off] = y;
}

// ---------------- final projection: out[b,o] = h[b, S-1, :] . W_fc[o,:] + b_fc[o] ----------------
__global__ void __launch_bounds__(512) final_kernel(const float* __restrict__ W,
                                                    const float* __restrict__ bias,
                                                    float* __restrict__ out) {
    int b = blockIdx.x;
    int o = threadIdx.x;
    const float* hv = g_h + (size_t)(b * SEQ + SEQ - 1) * DMODEL;
    const float4* w4 = (const float4*)(W + (size_t)o * DMODEL);
    const float4* h4 = (const float4*)hv;
    float acc = bias[o];
#pragma unroll
    for (int f = 0; f < DMODEL / 4; f++) {
        float4 a = h4[f], w = w4[f];
        acc += a.x * w.x + a.y * w.y + a.z * w.z + a.w * w.w;
    }
    out[b * IN_DIM + o] = acc;
}

// ---------------- host ----------------
extern "C" void kernel_launch(void* const* d_in, const int* in_sizes, int n_in,
                              void* d_out, int out_size) {
    const float* x      = (const float*)d_in[0];
    const float* W_in   = (const float*)d_in[1];
    const float* b_in   = (const float*)d_in[2];
    const float* qkv_w  = (const float*)d_in[3];
    const float* qkv_b  = (const float*)d_in[4];
    const float* out_w  = (const float*)d_in[5];
    const float* out_b  = (const float*)d_in[6];
    const float* ln1_w  = (const float*)d_in[7];
    const float* ln1_b  = (const float*)d_in[8];
    const float* ff1_w  = (const float*)d_in[9];
    const float* ff1_b  = (const float*)d_in[10];
    const float* ff2_w  = (const float*)d_in[11];
    const float* ff2_b  = (const float*)d_in[12];
    const float* ln2_w  = (const float*)d_in[13];
    const float* ln2_b  = (const float*)d_in[14];
    const float* W_fc   = (const float*)d_in[15];
    const float* b_fc   = (const float*)d_in[16];
    float* out = (float*)d_out;

    float *p_h, *p_qkv, *p_ctx, *p_sa, *p_ff;
    cudaGetSymbolAddress((void**)&p_h, g_h);
    cudaGetSymbolAddress((void**)&p_qkv, g_qkv);
    cudaGetSymbolAddress((void**)&p_ctx, g_ctx);
    cudaGetSymbolAddress((void**)&p_sa, g_sa);
    cudaGetSymbolAddress((void**)&p_ff, g_ff);

    // positional encoding table
    pe_kernel<<<(SEQ * DMODEL + 255) / 256, 256>>>();

    // input projection + PE:  h = x @ W_in^T + b_in + pe
    {
        dim3 grid(DMODEL / BN, NTOK / BM);
        gemm_nt<2><<<grid, 256>>>(x, W_in, b_in, p_h, NTOK, DMODEL, IN_DIM);
    }

    for (int l = 0; l < NLAYER; l++) {
        // qkv = h @ qkv_w^T + qkv_b
        {
            dim3 grid(3 * DMODEL / BN, NTOK / BM);
            gemm_nt<0><<<grid, 256>>>(p_h, qkv_w + (size_t)l * 3 * DMODEL * DMODEL,
                                      qkv_b + (size_t)l * 3 * DMODEL, p_qkv,
                                      NTOK, 3 * DMODEL, DMODEL);
        }
        // attention
        {
            dim3 grid(BATCH * NHEAD, SEQ / 128);
            flash_kernel<<<grid, 128>>>(p_qkv, p_ctx);
        }
        // out projection
        {
            dim3 grid(DMODEL / BN, NTOK / BM);
            gemm_nt<0><<<grid, 256>>>(p_ctx, out_w + (size_t)l * DMODEL * DMODEL,
                                      out_b + (size_t)l * DMODEL, p_sa,
                                      NTOK, DMODEL, DMODEL);
        }
        // h = LN(h + sa)
        ln_kernel<<<NTOK, 256>>>(p_sa, ln1_w + (size_t)l * DMODEL, ln1_b + (size_t)l * DMODEL);
        // ff = relu(h @ ff1_w^T + b)
        {
            dim3 grid(FFDIM / BN, NTOK / BM);
            gemm_nt<1><<<grid, 256>>>(p_h, ff1_w + (size_t)l * FFDIM * DMODEL,
                                      ff1_b + (size_t)l * FFDIM, p_ff,
                                      NTOK, FFDIM, DMODEL);
        }
        // sa = ff @ ff2_w^T + b
        {
            dim3 grid(DMODEL / BN, NTOK / BM);
            gemm_nt<0><<<grid, 256>>>(p_ff, ff2_w + (size_t)l * DMODEL * FFDIM,
                                      ff2_b + (size_t)l * DMODEL, p_sa,
                                      NTOK, DMODEL, FFDIM);
        }
        // h = LN(h + sa)
        ln_kernel<<<NTOK, 256>>>(p_sa, ln2_w + (size_t)l * DMODEL, ln2_b + (size_t)l * DMODEL);
    }

    // final projection from last timestep
    final_kernel<<<BATCH, IN_DIM>>>(W_fc, b_fc, out);
}

// round 2
// speedup vs baseline: 1.5492x; 1.5492x over previous
#include <cuda_runtime.h>
#include <cuda_fp16.h>
#include <math.h>
#include <stdint.h>

#define BATCH 4
#define SEQ 2048
#define IN_DIM 512
#define DMODEL 256
#define NHEAD 4
#define HDIM 64
#define NLAYER 4
#define FFDIM 2048
#define NTOK (BATCH * SEQ)   // 8192

// ---------------- scratch (device globals, no allocation) ----------------
__device__ float g_h[NTOK * DMODEL];
__device__ float g_qkv[NTOK * 3 * DMODEL];
__device__ float g_sa[NTOK * DMODEL];
__device__ float g_pe[SEQ * DMODEL];

__device__ __half g_x16[NTOK * IN_DIM];
__device__ __half g_h16[NTOK * DMODEL];
__device__ __half g_ctx16[NTOK * DMODEL];
__device__ __half g_ff16[NTOK * FFDIM];

__device__ __half g_win16[DMODEL * IN_DIM];
__device__ __half g_qkvw16[NLAYER * 3 * DMODEL * DMODEL];
__device__ __half g_outw16[NLAYER * DMODEL * DMODEL];
__device__ __half g_ff1w16[NLAYER * FFDIM * DMODEL];
__device__ __half g_ff2w16[NLAYER * DMODEL * FFDIM];

// ---------------- helpers ----------------
__device__ __forceinline__ uint32_t smem_u32(const void* p) {
    return (uint32_t)__cvta_generic_to_shared(p);
}
__device__ __forceinline__ void cp16(uint32_t dst, const void* src) {
    asm volatile("cp.async.cg.shared.global [%0], [%1], 16;\n" :: "r"(dst), "l"(src));
}
__device__ __forceinline__ void cp_commit() {
    asm volatile("cp.async.commit_group;\n" ::: "memory");
}
__device__ __forceinline__ void ldmx4(uint32_t* r, uint32_t addr) {
    asm volatile("ldmatrix.sync.aligned.m8n8.x4.shared.b16 {%0,%1,%2,%3}, [%4];\n"
                 : "=r"(r[0]), "=r"(r[1]), "=r"(r[2]), "=r"(r[3]) : "r"(addr));
}
__device__ __forceinline__ void mma16816(float* c, const uint32_t* a, const uint32_t* b) {
    asm volatile(
        "mma.sync.aligned.m16n8k16.row.col.f32.f16.f16.f32 "
        "{%0,%1,%2,%3}, {%4,%5,%6,%7}, {%8,%9}, {%0,%1,%2,%3};\n"
        : "+f"(c[0]), "+f"(c[1]), "+f"(c[2]), "+f"(c[3])
        : "r"(a[0]), "r"(a[1]), "r"(a[2]), "r"(a[3]), "r"(b[0]), "r"(b[1]));
}

// ---------------- conversions ----------------
__global__ void f2h_kernel(const float* __restrict__ src, __half* __restrict__ dst, int n2) {
    int i = blockIdx.x * blockDim.x + threadIdx.x;
    if (i >= n2) return;
    float2 v = ((const float2*)src)[i];
    ((half2*)dst)[i] = __floats2half2_rn(v.x, v.y);
}

// ---------------- positional encoding ----------------
__global__ void pe_kernel() {
    int idx = blockIdx.x * blockDim.x + threadIdx.x;
    if (idx >= SEQ * DMODEL) return;
    int s = idx / DMODEL;
    int d = idx % DMODEL;
    int i = d >> 1;
    float freq = __expf(-(float)(2 * i) * (9.210340371976184f / 256.0f));
    float v = (float)s * freq;
    g_pe[idx] = (d & 1) ? cosf(v) : sinf(v);
}

// ---------------- HMMA GEMM: C[m,n] = sum_k A[m,k]*B[n,k] + bias[n] ----------------
// EPI 0: bias -> C32 ; EPI 1: bias+relu -> C16 ; EPI 2: bias+PE -> C32 and C16
#define PADK 40   // halves per smem row (80B = 5*16B: 16B-aligned, odd in 16B units -> conflict-free)

template <int EPI>
__global__ void __launch_bounds__(256) hgemm(const __half* __restrict__ A,
                                             const __half* __restrict__ B,
                                             const float* __restrict__ bias,
                                             float* __restrict__ C32,
                                             __half* __restrict__ C16,
                                             int M, int N, int K) {
    __shared__ __half As[2][128][PADK];
    __shared__ __half Bs[2][128][PADK];

    const int tid = threadIdx.x, lane = tid & 31, warp = tid >> 5;
    const int wm = warp >> 2;   // 0..1 : 64 rows
    const int wn = warp & 3;    // 0..3 : 32 cols
    const int bm = blockIdx.y * 128, bn = blockIdx.x * 128;

    float acc[4][4][4];
#pragma unroll
    for (int i = 0; i < 4; i++)
#pragma unroll
        for (int j = 0; j < 4; j++)
#pragma unroll
            for (int q = 0; q < 4; q++) acc[i][j][q] = 0.0f;

    const __half* Ag = A + (size_t)bm * K;
    const __half* Bg = B + (size_t)bn * K;
    const int row_l = tid >> 2;      // 0..63
    const int cg = tid & 3;          // 16B chunk within 32 halves

    // prologue: tile 0
#pragma unroll
    for (int p = 0; p < 2; p++) {
        int r = row_l + p * 64;
        cp16(smem_u32(&As[0][r][cg * 8]), Ag + (size_t)r * K + cg * 8);
        cp16(smem_u32(&Bs[0][r][cg * 8]), Bg + (size_t)r * K + cg * 8);
    }
    cp_commit();

    const int NKT = K >> 5;
    for (int kt = 0; kt < NKT; kt++) {
        int cur = kt & 1;
        if (kt + 1 < NKT) {
            const __half* Ag2 = Ag + (kt + 1) * 32;
            const __half* Bg2 = Bg + (kt + 1) * 32;
#pragma unroll
            for (int p = 0; p < 2; p++) {
                int r = row_l + p * 64;
                cp16(smem_u32(&As[cur ^ 1][r][cg * 8]), Ag2 + (size_t)r * K + cg * 8);
                cp16(smem_u32(&Bs[cur ^ 1][r][cg * 8]), Bg2 + (size_t)r * K + cg * 8);
            }
            cp_commit();
            asm volatile("cp.async.wait_group 1;\n" ::: "memory");
        } else {
            asm volatile("cp.async.wait_group 0;\n" ::: "memory");
        }
        __syncthreads();

#pragma unroll
        for (int ks = 0; ks < 2; ks++) {
            const int k0 = ks * 16;
            uint32_t a[4][4], b[2][4];
#pragma unroll
            for (int mt = 0; mt < 4; mt++) {
                int r = wm * 64 + mt * 16 + (lane & 15);
                int c = k0 + (lane >> 4) * 8;
                ldmx4(a[mt], smem_u32(&As[cur][r][c]));
            }
#pragma unroll
            for (int np = 0; np < 2; np++) {
                int r = wn * 32 + np * 16 + (lane & 7) + (lane >> 4) * 8;
                int c = k0 + ((lane >> 3) & 1) * 8;
                ldmx4(b[np], smem_u32(&Bs[cur][r][c]));
            }
#pragma unroll
            for (int mt = 0; mt < 4; mt++)
#pragma unroll
                for (int nt = 0; nt < 4; nt++)
                    mma16816(acc[mt][nt], a[mt], &b[nt >> 1][(nt & 1) * 2]);
        }
        __syncthreads();
    }

    // epilogue
#pragma unroll
    for (int mt = 0; mt < 4; mt++) {
#pragma unroll
        for (int nt = 0; nt < 4; nt++) {
            int row0 = bm + wm * 64 + mt * 16 + (lane >> 2);
            int col0 = bn + wn * 32 + nt * 8 + (lane & 3) * 2;
            float b0 = bias[col0], b1 = bias[col0 + 1];
#pragma unroll
            for (int hh = 0; hh < 2; hh++) {
                int row = row0 + hh * 8;
                float v0 = acc[mt][nt][hh * 2 + 0] + b0;
                float v1 = acc[mt][nt][hh * 2 + 1] + b1;
                if (EPI == 1) { v0 = fmaxf(v0, 0.0f); v1 = fmaxf(v1, 0.0f); }
                if (EPI == 2) {
                    v0 += g_pe[(row & (SEQ - 1)) * DMODEL + col0];
                    v1 += g_pe[(row & (SEQ - 1)) * DMODEL + col0 + 1];
                }
                size_t off = (size_t)row * N + col0;
                if (EPI == 0 || EPI == 2) {
                    float2 f2 = make_float2(v0, v1);
                    *(float2*)(C32 + off) = f2;
                }
                if (EPI == 1 || EPI == 2) {
                    *(half2*)(C16 + off) = __floats2half2_rn(v0, v1);
                }
            }
        }
    }
}

// ---------------- flash attention v2 ----------------
// grid: (B*H, SEQ/64), block 128 threads. 2 threads per query (32 dims each).
#define KT 32
__global__ void __launch_bounds__(128) flash2(const float* __restrict__ qkv,
                                              __half* __restrict__ ctx16) {
    const int bh = blockIdx.x;   // 0..15
    const int qt = blockIdx.y;   // 0..31
    const int b = bh >> 2;
    const int hh = bh & 3;
    const int tid = threadIdx.x, lane = tid & 31, warp = tid >> 5;
    const int q_local = warp * 16 + (lane & 15);
    const int half_id = lane >> 4;                // which 32-dim half
    const int q_token = b * SEQ + qt * 64 + q_local;
    const float scale = 0.125f;

    // [key][half][9] float4 layout: halves 9 float4 apart -> disjoint banks
    __shared__ float4 sk[KT * 18];
    __shared__ float4 sv[KT * 18];

    float4 q[8];
    const float4* qp = (const float4*)(qkv + (size_t)q_token * 768 + hh * HDIM + half_id * 32);
#pragma unroll
    for (int f = 0; f < 8; f++) {
        float4 t = qp[f];
        q[f] = make_float4(t.x * scale, t.y * scale, t.z * scale, t.w * scale);
    }

    float m = -1e30f, l = 0.0f;
    float4 ctx[8];
#pragma unroll
    for (int f = 0; f < 8; f++) ctx[f] = make_float4(0.f, 0.f, 0.f, 0.f);

    float sreg[KT];

    for (int kt = 0; kt < SEQ / KT; kt++) {
        const int kbase = b * SEQ + kt * KT;
        // load K/V tile: KT*16 float4 each; 128 threads x 4 each
#pragma unroll
        for (int i = 0; i < 4; i++) {
            int idx = i * 128 + tid;
            int key = idx >> 4;
            int f = idx & 15;
            int sidx = key * 18 + (f >> 3) * 9 + (f & 7);
            const float* rowp = qkv + (size_t)(kbase + key) * 768 + DMODEL + hh * HDIM;
            sk[sidx] = ((const float4*)rowp)[f];
            sv[sidx] = ((const float4*)(rowp + DMODEL))[f];
        }
        __syncthreads();

        float tmax = -1e30f;
#pragma unroll
        for (int j = 0; j < KT; j++) {
            float s = 0.0f;
            const float4* kp = &sk[j * 18 + half_id * 9];
#pragma unroll
            for (int f = 0; f < 8; f++) {
                float4 kv = kp[f];
                s += q[f].x * kv.x + q[f].y * kv.y + q[f].z * kv.z + q[f].w * kv.w;
            }
            s += __shfl_xor_sync(0xffffffffu, s, 16);
            sreg[j] = s;
            tmax = fmaxf(tmax, s);
        }

        float nm = fmaxf(m, tmax);
        float corr = __expf(m - nm);
        l *= corr;
#pragma unroll
        for (int f = 0; f < 8; f++) {
            ctx[f].x *= corr; ctx[f].y *= corr; ctx[f].z *= corr; ctx[f].w *= corr;
        }

#pragma unroll
        for (int j = 0; j < KT; j++) {
            float p = __expf(sreg[j] - nm);
            l += p;
            const float4* vp = &sv[j * 18 + half_id * 9];
#pragma unroll
            for (int f = 0; f < 8; f++) {
                float4 vv = vp[f];
                ctx[f].x += p * vv.x; ctx[f].y += p * vv.y;
                ctx[f].z += p * vv.z; ctx[f].w += p * vv.w;
            }
        }
        m = nm;
        __syncthreads();
    }

    float inv = 1.0f / l;
    __half* outp = ctx16 + (size_t)q_token * DMODEL + hh * HDIM + half_id * 32;
#pragma unroll
    for (int f = 0; f < 8; f++) {
        ((half2*)outp)[f * 2 + 0] = __floats2half2_rn(ctx[f].x * inv, ctx[f].y * inv);
        ((half2*)outp)[f * 2 + 1] = __floats2half2_rn(ctx[f].z * inv, ctx[f].w * inv);
    }
}

// ---------------- residual + layernorm (in-place into g_h, dual write fp16) ----------------
__global__ void __launch_bounds__(256) ln_kernel(const float* __restrict__ res,
                                                 const float* __restrict__ w,
                                                 const float* __restrict__ b) {
    int t = blockIdx.x;
    int i = threadIdx.x;
    size_t off = (size_t)t * DMODEL + i;
    float x = g_h[off] + res[off];

    float s = x, s2 = x * x;
#pragma unroll
    for (int o = 16; o > 0; o >>= 1) {
        s  += __shfl_xor_sync(0xffffffffu, s, o);
        s2 += __shfl_xor_sync(0xffffffffu, s2, o);
    }
    __shared__ float red[2][8];
    int warp = i >> 5, lane = i & 31;
    if (lane == 0) { red[0][warp] = s; red[1][warp] = s2; }
    __syncthreads();
    if (warp == 0) {
        float a = (lane < 8) ? red[0][lane] : 0.0f;
        float a2 = (lane < 8) ? red[1][lane] : 0.0f;
#pragma unroll
        for (int o = 4; o > 0; o >>= 1) {
            a  += __shfl_xor_sync(0xffffffffu, a, o);
            a2 += __shfl_xor_sync(0xffffffffu, a2, o);
        }
        if (lane == 0) { red[0][0] = a; red[1][0] = a2; }
    }
    __syncthreads();
    float mu = red[0][0] * (1.0f / DMODEL);
    float var = red[1][0] * (1.0f / DMODEL) - mu * mu;
    float y = (x - mu) * rsqrtf(var + 1e-5f) * w[i] + b[i];
    g_h[off] = y;
    g_h16[off] = __float2half(y);
}

// ---------------- final projection ----------------
__global__ void __launch_bounds__(512) final_kernel(const float* __restrict__ W,
                                                    const float* __restrict__ bias,
                                                    float* __restrict__ out) {
    int b = blockIdx.x;
    int o = threadIdx.x;
    const float* hv = g_h + (size_t)(b * SEQ + SEQ - 1) * DMODEL;
    const float4* w4 = (const float4*)(W + (size_t)o * DMODEL);
    const float4* h4 = (const float4*)hv;
    float acc = bias[o];
#pragma unroll
    for (int f = 0; f < DMODEL / 4; f++) {
        float4 a = h4[f], w = w4[f];
        acc += a.x * w.x + a.y * w.y + a.z * w.z + a.w * w.w;
    }
    out[b * IN_DIM + o] = acc;
}

// ---------------- host ----------------
static void conv(const float* src, __half* dst, int n) {
    int n2 = n / 2;
    f2h_kernel<<<(n2 + 255) / 256, 256>>>(src, dst, n2);
}

extern "C" void kernel_launch(void* const* d_in, const int* in_sizes, int n_in,
                              void* d_out, int out_size) {
    const float* x      = (const float*)d_in[0];
    const float* W_in   = (const float*)d_in[1];
    const float* b_in   = (const float*)d_in[2];
    const float* qkv_w  = (const float*)d_in[3];
    const float* qkv_b  = (const float*)d_in[4];
    const float* out_w  = (const float*)d_in[5];
    const float* out_b  = (const float*)d_in[6];
    const float* ln1_w  = (const float*)d_in[7];
    const float* ln1_b  = (const float*)d_in[8];
    const float* ff1_w  = (const float*)d_in[9];
    const float* ff1_b  = (const float*)d_in[10];
    const float* ff2_w  = (const float*)d_in[11];
    const float* ff2_b  = (const float*)d_in[12];
    const float* ln2_w  = (const float*)d_in[13];
    const float* ln2_b  = (const float*)d_in[14];
    const float* W_fc   = (const float*)d_in[15];
    const float* b_fc   = (const float*)d_in[16];
    float* out = (float*)d_out;

    float *p_h, *p_qkv, *p_sa;
    __half *p_x16, *p_h16, *p_ctx16, *p_ff16;
    __half *p_win16, *p_qkvw16, *p_outw16, *p_ff1w16, *p_ff2w16;
    cudaGetSymbolAddress((void**)&p_h, g_h);
    cudaGetSymbolAddress((void**)&p_qkv, g_qkv);
    cudaGetSymbolAddress((void**)&p_sa, g_sa);
    cudaGetSymbolAddress((void**)&p_x16, g_x16);
    cudaGetSymbolAddress((void**)&p_h16, g_h16);
    cudaGetSymbolAddress((void**)&p_ctx16, g_ctx16);
    cudaGetSymbolAddress((void**)&p_ff16, g_ff16);
    cudaGetSymbolAddress((void**)&p_win16, g_win16);
    cudaGetSymbolAddress((void**)&p_qkvw16, g_qkvw16);
    cudaGetSymbolAddress((void**)&p_outw16, g_outw16);
    cudaGetSymbolAddress((void**)&p_ff1w16, g_ff1w16);
    cudaGetSymbolAddress((void**)&p_ff2w16, g_ff2w16);

    pe_kernel<<<(SEQ * DMODEL + 255) / 256, 256>>>();

    // fp16 conversions
    conv(x, p_x16, NTOK * IN_DIM);
    conv(W_in, p_win16, DMODEL * IN_DIM);
    conv(qkv_w, p_qkvw16, NLAYER * 3 * DMODEL * DMODEL);
    conv(out_w, p_outw16, NLAYER * DMODEL * DMODEL);
    conv(ff1_w, p_ff1w16, NLAYER * FFDIM * DMODEL);
    conv(ff2_w, p_ff2w16, NLAYER * DMODEL * FFDIM);

    // input projection + PE: h (fp32 + fp16)
    {
        dim3 grid(DMODEL / 128, NTOK / 128);
        hgemm<2><<<grid, 256>>>(p_x16, p_win16, b_in, p_h, p_h16, NTOK, DMODEL, IN_DIM);
    }

    for (int l = 0; l < NLAYER; l++) {
        // qkv (fp32 out for attention)
        {
            dim3 grid(3 * DMODEL / 128, NTOK / 128);
            hgemm<0><<<grid, 256>>>(p_h16, p_qkvw16 + (size_t)l * 3 * DMODEL * DMODEL,
                                    qkv_b + (size_t)l * 3 * DMODEL, p_qkv, nullptr,
                                    NTOK, 3 * DMODEL, DMODEL);
        }
        // attention -> ctx fp16
        {
            dim3 grid(BATCH * NHEAD, SEQ / 64);
            flash2<<<grid, 128>>>(p_qkv, p_ctx16);
        }
        // out projection -> sa fp32
        {
            dim3 grid(DMODEL / 128, NTOK / 128);
            hgemm<0><<<grid, 256>>>(p_ctx16, p_outw16 + (size_t)l * DMODEL * DMODEL,
                                    out_b + (size_t)l * DMODEL, p_sa, nullptr,
                                    NTOK, DMODEL, DMODEL);
        }
        ln_kernel<<<NTOK, 256>>>(p_sa, ln1_w + (size_t)l * DMODEL, ln1_b + (size_t)l * DMODEL);
        // ff1 (relu) -> fp16 only
        {
            dim3 grid(FFDIM / 128, NTOK / 128);
            hgemm<1><<<grid, 256>>>(p_h16, p_ff1w16 + (size_t)l * FFDIM * DMODEL,
                                    ff1_b + (size_t)l * FFDIM, nullptr, p_ff16,
                                    NTOK, FFDIM, DMODEL);
        }
        // ff2 -> sa fp32
        {
            dim3 grid(DMODEL / 128, NTOK / 128);
            hgemm<0><<<grid, 256>>>(p_ff16, p_ff2w16 + (size_t)l * DMODEL * FFDIM,
                                    ff2_b + (size_t)l * DMODEL, p_sa, nullptr,
                                    NTOK, DMODEL, FFDIM);
        }
        ln_kernel<<<NTOK, 256>>>(p_sa, ln2_w + (size_t)l * DMODEL, ln2_b + (size_t)l * DMODEL);
    }

    final_kernel<<<BATCH, IN_DIM>>>(W_fc, b_fc, out);
}

// round 3
// speedup vs baseline: 6.1022x; 3.9388x over previous
#include <cuda_runtime.h>
#include <cuda_fp16.h>
#include <math.h>
#include <stdint.h>

#define BATCH 4
#define SEQ 2048
#define IN_DIM 512
#define DMODEL 256
#define NHEAD 4
#define HDIM 64
#define NLAYER 4
#define FFDIM 2048
#define NTOK (BATCH * SEQ)   // 8192

// ---------------- scratch (device globals, no allocation) ----------------
__device__ float g_h[NTOK * DMODEL];
__device__ float g_sa[NTOK * DMODEL];
__device__ float g_pe[SEQ * DMODEL];

__device__ __half g_x16[NTOK * IN_DIM];
__device__ __half g_h16[NTOK * DMODEL];
__device__ __half g_qkv16[NTOK * 3 * DMODEL];
__device__ __half g_ctx16[NTOK * DMODEL];
__device__ __half g_ff16[NTOK * FFDIM];

__device__ __half g_win16[DMODEL * IN_DIM];
__device__ __half g_qkvw16[NLAYER * 3 * DMODEL * DMODEL];
__device__ __half g_outw16[NLAYER * DMODEL * DMODEL];
__device__ __half g_ff1w16[NLAYER * FFDIM * DMODEL];
__device__ __half g_ff2w16[NLAYER * DMODEL * FFDIM];

// ---------------- helpers ----------------
__device__ __forceinline__ uint32_t smem_u32(const void* p) {
    return (uint32_t)__cvta_generic_to_shared(p);
}
__device__ __forceinline__ void cp16(uint32_t dst, const void* src) {
    asm volatile("cp.async.cg.shared.global [%0], [%1], 16;\n" :: "r"(dst), "l"(src));
}
__device__ __forceinline__ void cp_commit() {
    asm volatile("cp.async.commit_group;\n" ::: "memory");
}
__device__ __forceinline__ void ldmx4(uint32_t* r, uint32_t addr) {
    asm volatile("ldmatrix.sync.aligned.m8n8.x4.shared.b16 {%0,%1,%2,%3}, [%4];\n"
                 : "=r"(r[0]), "=r"(r[1]), "=r"(r[2]), "=r"(r[3]) : "r"(addr));
}
__device__ __forceinline__ void ldmx4t(uint32_t* r, uint32_t addr) {
    asm volatile("ldmatrix.sync.aligned.m8n8.x4.trans.shared.b16 {%0,%1,%2,%3}, [%4];\n"
                 : "=r"(r[0]), "=r"(r[1]), "=r"(r[2]), "=r"(r[3]) : "r"(addr));
}
__device__ __forceinline__ void mma16816(float* c, const uint32_t* a, const uint32_t* b) {
    asm volatile(
        "mma.sync.aligned.m16n8k16.row.col.f32.f16.f16.f32 "
        "{%0,%1,%2,%3}, {%4,%5,%6,%7}, {%8,%9}, {%0,%1,%2,%3};\n"
        : "+f"(c[0]), "+f"(c[1]), "+f"(c[2]), "+f"(c[3])
        : "r"(a[0]), "r"(a[1]), "r"(a[2]), "r"(a[3]), "r"(b[0]), "r"(b[1]));
}

// ---------------- conversions ----------------
__global__ void f2h_kernel(const float* __restrict__ src, __half* __restrict__ dst, int n2) {
    int i = blockIdx.x * blockDim.x + threadIdx.x;
    if (i >= n2) return;
    float2 v = ((const float2*)src)[i];
    ((half2*)dst)[i] = __floats2half2_rn(v.x, v.y);
}

// ---------------- positional encoding ----------------
__global__ void pe_kernel() {
    int idx = blockIdx.x * blockDim.x + threadIdx.x;
    if (idx >= SEQ * DMODEL) return;
    int s = idx / DMODEL;
    int d = idx % DMODEL;
    int i = d >> 1;
    float freq = __expf(-(float)(2 * i) * (9.210340371976184f / 256.0f));
    float v = (float)s * freq;
    g_pe[idx] = (d & 1) ? cosf(v) : sinf(v);
}

// ---------------- HMMA GEMM: C[m,n] = sum_k A[m,k]*B[n,k] + bias[n] ----------------
// EPI 0: bias -> C32 ; EPI 1: bias+relu -> C16 ; EPI 2: bias+PE -> C32 & C16 ; EPI 3: bias -> C16
#define PADK 40

template <int EPI>
__global__ void __launch_bounds__(256) hgemm(const __half* __restrict__ A,
                                             const __half* __restrict__ B,
                                             const float* __restrict__ bias,
                                             float* __restrict__ C32,
                                             __half* __restrict__ C16,
                                             int M, int N, int K) {
    __shared__ __half As[2][128][PADK];
    __shared__ __half Bs[2][128][PADK];

    const int tid = threadIdx.x, lane = tid & 31, warp = tid >> 5;
    const int wm = warp >> 2;
    const int wn = warp & 3;
    const int bm = blockIdx.y * 128, bn = blockIdx.x * 128;

    float acc[4][4][4];
#pragma unroll
    for (int i = 0; i < 4; i++)
#pragma unroll
        for (int j = 0; j < 4; j++)
#pragma unroll
            for (int q = 0; q < 4; q++) acc[i][j][q] = 0.0f;

    const __half* Ag = A + (size_t)bm * K;
    const __half* Bg = B + (size_t)bn * K;
    const int row_l = tid >> 2;
    const int cg = tid & 3;

#pragma unroll
    for (int p = 0; p < 2; p++) {
        int r = row_l + p * 64;
        cp16(smem_u32(&As[0][r][cg * 8]), Ag + (size_t)r * K + cg * 8);
        cp16(smem_u32(&Bs[0][r][cg * 8]), Bg + (size_t)r * K + cg * 8);
    }
    cp_commit();

    const int NKT = K >> 5;
    for (int kt = 0; kt < NKT; kt++) {
        int cur = kt & 1;
        if (kt + 1 < NKT) {
            const __half* Ag2 = Ag + (kt + 1) * 32;
            const __half* Bg2 = Bg + (kt + 1) * 32;
#pragma unroll
            for (int p = 0; p < 2; p++) {
                int r = row_l + p * 64;
                cp16(smem_u32(&As[cur ^ 1][r][cg * 8]), Ag2 + (size_t)r * K + cg * 8);
                cp16(smem_u32(&Bs[cur ^ 1][r][cg * 8]), Bg2 + (size_t)r * K + cg * 8);
            }
            cp_commit();
            asm volatile("cp.async.wait_group 1;\n" ::: "memory");
        } else {
            asm volatile("cp.async.wait_group 0;\n" ::: "memory");
        }
        __syncthreads();

#pragma unroll
        for (int ks = 0; ks < 2; ks++) {
            const int k0 = ks * 16;
            uint32_t a[4][4], b[2][4];
#pragma unroll
            for (int mt = 0; mt < 4; mt++) {
                int r = wm * 64 + mt * 16 + (lane & 15);
                int c = k0 + (lane >> 4) * 8;
                ldmx4(a[mt], smem_u32(&As[cur][r][c]));
            }
#pragma unroll
            for (int np = 0; np < 2; np++) {
                int r = wn * 32 + np * 16 + (lane & 7) + (lane >> 4) * 8;
                int c = k0 + ((lane >> 3) & 1) * 8;
                ldmx4(b[np], smem_u32(&Bs[cur][r][c]));
            }
#pragma unroll
            for (int mt = 0; mt < 4; mt++)
#pragma unroll
                for (int nt = 0; nt < 4; nt++)
                    mma16816(acc[mt][nt], a[mt], &b[nt >> 1][(nt & 1) * 2]);
        }
        __syncthreads();
    }

#pragma unroll
    for (int mt = 0; mt < 4; mt++) {
#pragma unroll
        for (int nt = 0; nt < 4; nt++) {
            int row0 = bm + wm * 64 + mt * 16 + (lane >> 2);
            int col0 = bn + wn * 32 + nt * 8 + (lane & 3) * 2;
            float b0 = bias[col0], b1 = bias[col0 + 1];
#pragma unroll
            for (int hh = 0; hh < 2; hh++) {
                int row = row0 + hh * 8;
                float v0 = acc[mt][nt][hh * 2 + 0] + b0;
                float v1 = acc[mt][nt][hh * 2 + 1] + b1;
                if (EPI == 1) { v0 = fmaxf(v0, 0.0f); v1 = fmaxf(v1, 0.0f); }
                if (EPI == 2) {
                    v0 += g_pe[(row & (SEQ - 1)) * DMODEL + col0];
                    v1 += g_pe[(row & (SEQ - 1)) * DMODEL + col0 + 1];
                }
                size_t off = (size_t)row * N + col0;
                if (EPI == 0 || EPI == 2) {
                    *(float2*)(C32 + off) = make_float2(v0, v1);
                }
                if (EPI == 1 || EPI == 2 || EPI == 3) {
                    *(half2*)(C16 + off) = __floats2half2_rn(v0, v1);
                }
            }
        }
    }
}

// ---------------- tensor-core flash attention (FA2) ----------------
// grid (B*H, SEQ/64), 128 threads = 4 warps. Warp w owns query rows w*16..w*16+15.
// K/V tiles of 64 keys, double buffered. Rows padded to 72 halves.
#define PADR 72
__global__ void __launch_bounds__(128) flash_mma(const __half* __restrict__ qkv16,
                                                 __half* __restrict__ ctx16) {
    __shared__ __half sk[2][64][PADR];
    __shared__ __half sv[2][64][PADR];

    const int bh = blockIdx.x;
    const int qt = blockIdx.y;
    const int b = bh >> 2;
    const int hh = bh & 3;
    const int tid = threadIdx.x, lane = tid & 31, warp = tid >> 5;
    const float scale = 0.125f;

    const int q_row0 = b * SEQ + qt * 64;  // token of query row 0
    const __half* qbase = qkv16 + (size_t)q_row0 * 768 + hh * HDIM;           // Q
    const __half* kbase = qkv16 + (size_t)(b * SEQ) * 768 + DMODEL + hh * HDIM;  // K
    const __half* vbase = kbase + DMODEL;                                     // V

    // ---- stage Q into sk[0], extract A fragments ----
    {
        const int r = tid >> 1;          // 0..63
        const int c = (tid & 1) * 4;     // chunk pairs: 8 chunks per row, 2 threads/row x 4
#pragma unroll
        for (int i = 0; i < 4; i++)
            cp16(smem_u32(&sk[0][r][(c + i) * 8]), qbase + (size_t)r * 768 + (c + i) * 8);
        cp_commit();
        asm volatile("cp.async.wait_group 0;\n" ::: "memory");
        __syncthreads();
    }
    uint32_t qf[4][4];
#pragma unroll
    for (int ks = 0; ks < 4; ks++) {
        int r = warp * 16 + (lane & 15);
        int c = ks * 16 + (lane >> 4) * 8;
        ldmx4(qf[ks], smem_u32(&sk[0][r][c]));
    }
    __syncthreads();

    // ---- online softmax state ----
    float m0 = -1e30f, m1 = -1e30f, l0 = 0.0f, l1 = 0.0f;
    float o[8][4];
#pragma unroll
    for (int nt = 0; nt < 8; nt++)
#pragma unroll
        for (int i = 0; i < 4; i++) o[nt][i] = 0.0f;

    // ---- prologue: load K/V tile 0 ----
    const int lrow = tid >> 1;
    const int lcg = (tid & 1) * 4;
#pragma unroll
    for (int i = 0; i < 4; i++) {
        cp16(smem_u32(&sk[0][lrow][(lcg + i) * 8]), kbase + (size_t)lrow * 768 + (lcg + i) * 8);
        cp16(smem_u32(&sv[0][lrow][(lcg + i) * 8]), vbase + (size_t)lrow * 768 + (lcg + i) * 8);
    }
    cp_commit();

    const int NT = SEQ / 64;
    for (int kt = 0; kt < NT; kt++) {
        const int cur = kt & 1;
        if (kt + 1 < NT) {
            const __half* k2 = kbase + (size_t)(kt + 1) * 64 * 768;
            const __half* v2 = vbase + (size_t)(kt + 1) * 64 * 768;
#pragma unroll
            for (int i = 0; i < 4; i++) {
                cp16(smem_u32(&sk[cur ^ 1][lrow][(lcg + i) * 8]), k2 + (size_t)lrow * 768 + (lcg + i) * 8);
                cp16(smem_u32(&sv[cur ^ 1][lrow][(lcg + i) * 8]), v2 + (size_t)lrow * 768 + (lcg + i) * 8);
            }
            cp_commit();
            asm volatile("cp.async.wait_group 1;\n" ::: "memory");
        } else {
            asm volatile("cp.async.wait_group 0;\n" ::: "memory");
        }
        __syncthreads();

        // ---- S = Q K^T (16x64 per warp) ----
        float s[8][4];
#pragma unroll
        for (int nt = 0; nt < 8; nt++)
#pragma unroll
            for (int i = 0; i < 4; i++) s[nt][i] = 0.0f;

#pragma unroll
        for (int ks = 0; ks < 4; ks++) {
            uint32_t bk[4][4];
#pragma unroll
            for (int kg = 0; kg < 4; kg++) {
                int r = kg * 16 + (lane & 7) + (lane >> 4) * 8;
                int c = ks * 16 + ((lane >> 3) & 1) * 8;
                ldmx4(bk[kg], smem_u32(&sk[cur][r][c]));
            }
#pragma unroll
            for (int nt = 0; nt < 8; nt++)
                mma16816(s[nt], qf[ks], &bk[nt >> 1][(nt & 1) * 2]);
        }

        // ---- scale + online softmax ----
        float mx0 = -1e30f, mx1 = -1e30f;
#pragma unroll
        for (int nt = 0; nt < 8; nt++) {
#pragma unroll
            for (int i = 0; i < 4; i++) s[nt][i] *= scale;
            mx0 = fmaxf(mx0, fmaxf(s[nt][0], s[nt][1]));
            mx1 = fmaxf(mx1, fmaxf(s[nt][2], s[nt][3]));
        }
        mx0 = fmaxf(mx0, __shfl_xor_sync(0xffffffffu, mx0, 1));
        mx0 = fmaxf(mx0, __shfl_xor_sync(0xffffffffu, mx0, 2));
        mx1 = fmaxf(mx1, __shfl_xor_sync(0xffffffffu, mx1, 1));
        mx1 = fmaxf(mx1, __shfl_xor_sync(0xffffffffu, mx1, 2));

        float nm0 = fmaxf(m0, mx0), nm1 = fmaxf(m1, mx1);
        float cor0 = __expf(m0 - nm0), cor1 = __expf(m1 - nm1);
        m0 = nm0; m1 = nm1;

        float rs0 = 0.0f, rs1 = 0.0f;
#pragma unroll
        for (int nt = 0; nt < 8; nt++) {
            s[nt][0] = __expf(s[nt][0] - nm0);
            s[nt][1] = __expf(s[nt][1] - nm0);
            s[nt][2] = __expf(s[nt][2] - nm1);
            s[nt][3] = __expf(s[nt][3] - nm1);
            rs0 += s[nt][0] + s[nt][1];
            rs1 += s[nt][2] + s[nt][3];
        }
        rs0 += __shfl_xor_sync(0xffffffffu, rs0, 1);
        rs0 += __shfl_xor_sync(0xffffffffu, rs0, 2);
        rs1 += __shfl_xor_sync(0xffffffffu, rs1, 1);
        rs1 += __shfl_xor_sync(0xffffffffu, rs1, 2);
        l0 = l0 * cor0 + rs0;
        l1 = l1 * cor1 + rs1;

#pragma unroll
        for (int nt = 0; nt < 8; nt++) {
            o[nt][0] *= cor0; o[nt][1] *= cor0;
            o[nt][2] *= cor1; o[nt][3] *= cor1;
        }

        // ---- P fragments (fp16) ----
        uint32_t pf[4][4];
#pragma unroll
        for (int ks = 0; ks < 4; ks++) {
            half2 h;
            h = __floats2half2_rn(s[2 * ks][0], s[2 * ks][1]);     pf[ks][0] = *(uint32_t*)&h;
            h = __floats2half2_rn(s[2 * ks][2], s[2 * ks][3]);     pf[ks][1] = *(uint32_t*)&h;
            h = __floats2half2_rn(s[2 * ks + 1][0], s[2 * ks + 1][1]); pf[ks][2] = *(uint32_t*)&h;
            h = __floats2half2_rn(s[2 * ks + 1][2], s[2 * ks + 1][3]); pf[ks][3] = *(uint32_t*)&h;
        }

        // ---- O += P V  (V^T fragments via ldmatrix.trans) ----
#pragma unroll
        for (int ks = 0; ks < 4; ks++) {
            uint32_t bv[4][4];
#pragma unroll
            for (int dg = 0; dg < 4; dg++) {
                int r = ks * 16 + (lane & 7) + ((lane >> 3) & 1) * 8;
                int c = dg * 16 + (lane >> 4) * 8;
                ldmx4t(bv[dg], smem_u32(&sv[cur][r][c]));
            }
#pragma unroll
            for (int nt = 0; nt < 8; nt++)
                mma16816(o[nt], pf[ks], &bv[nt >> 1][(nt & 1) * 2]);
        }
        __syncthreads();
    }

    // ---- normalize + write ----
    float inv0 = 1.0f / l0, inv1 = 1.0f / l1;
    int r0 = warp * 16 + (lane >> 2);
    __half* out0 = ctx16 + (size_t)(q_row0 + r0) * DMODEL + hh * HDIM;
    __half* out1 = ctx16 + (size_t)(q_row0 + r0 + 8) * DMODEL + hh * HDIM;
#pragma unroll
    for (int nt = 0; nt < 8; nt++) {
        int c = nt * 8 + (lane & 3) * 2;
        *(half2*)(out0 + c) = __floats2half2_rn(o[nt][0] * inv0, o[nt][1] * inv0);
        *(half2*)(out1 + c) = __floats2half2_rn(o[nt][2] * inv1, o[nt][3] * inv1);
    }
}

// ---------------- residual + layernorm ----------------
__global__ void __launch_bounds__(256) ln_kernel(const float* __restrict__ res,
                                                 const float* __restrict__ w,
                                                 const float* __restrict__ b) {
    int t = blockIdx.x;
    int i = threadIdx.x;
    size_t off = (size_t)t * DMODEL + i;
    float x = g_h[off] + res[off];

    float s = x, s2 = x * x;
#pragma unroll
    for (int o = 16; o > 0; o >>= 1) {
        s  += __shfl_xor_sync(0xffffffffu, s, o);
        s2 += __shfl_xor_sync(0xffffffffu, s2, o);
    }
    __shared__ float red[2][8];
    int warp = i >> 5, lane = i & 31;
    if (lane == 0) { red[0][warp] = s; red[1][warp] = s2; }
    __syncthreads();
    if (warp == 0) {
        float a = (lane < 8) ? red[0][lane] : 0.0f;
        float a2 = (lane < 8) ? red[1][lane] : 0.0f;
#pragma unroll
        for (int o = 4; o > 0; o >>= 1) {
            a  += __shfl_xor_sync(0xffffffffu, a, o);
            a2 += __shfl_xor_sync(0xffffffffu, a2, o);
        }
        if (lane == 0) { red[0][0] = a; red[1][0] = a2; }
    }
    __syncthreads();
    float mu = red[0][0] * (1.0f / DMODEL);
    float var = red[1][0] * (1.0f / DMODEL) - mu * mu;
    float y = (x - mu) * rsqrtf(var + 1e-5f) * w[i] + b[i];
    g_h[off] = y;
    g_h16[off] = __float2half(y);
}

// ---------------- final projection ----------------
__global__ void __launch_bounds__(512) final_kernel(const float* __restrict__ W,
                                                    const float* __restrict__ bias,
                                                    float* __restrict__ out) {
    int b = blockIdx.x;
    int o = threadIdx.x;
    const float* hv = g_h + (size_t)(b * SEQ + SEQ - 1) * DMODEL;
    const float4* w4 = (const float4*)(W + (size_t)o * DMODEL);
    const float4* h4 = (const float4*)hv;
    float acc = bias[o];
#pragma unroll
    for (int f = 0; f < DMODEL / 4; f++) {
        float4 a = h4[f], w = w4[f];
        acc += a.x * w.x + a.y * w.y + a.z * w.z + a.w * w.w;
    }
    out[b * IN_DIM + o] = acc;
}

// ---------------- host ----------------
static void conv(const float* src, __half* dst, int n) {
    int n2 = n / 2;
    f2h_kernel<<<(n2 + 255) / 256, 256>>>(src, dst, n2);
}

extern "C" void kernel_launch(void* const* d_in, const int* in_sizes, int n_in,
                              void* d_out, int out_size) {
    const float* x      = (const float*)d_in[0];
    const float* W_in   = (const float*)d_in[1];
    const float* b_in   = (const float*)d_in[2];
    const float* qkv_w  = (const float*)d_in[3];
    const float* qkv_b  = (const float*)d_in[4];
    const float* out_w  = (const float*)d_in[5];
    const float* out_b  = (const float*)d_in[6];
    const float* ln1_w  = (const float*)d_in[7];
    const float* ln1_b  = (const float*)d_in[8];
    const float* ff1_w  = (const float*)d_in[9];
    const float* ff1_b  = (const float*)d_in[10];
    const float* ff2_w  = (const float*)d_in[11];
    const float* ff2_b  = (const float*)d_in[12];
    const float* ln2_w  = (const float*)d_in[13];
    const float* ln2_b  = (const float*)d_in[14];
    const float* W_fc   = (const float*)d_in[15];
    const float* b_fc   = (const float*)d_in[16];
    float* out = (float*)d_out;

    float *p_h, *p_sa;
    __half *p_x16, *p_h16, *p_qkv16, *p_ctx16, *p_ff16;
    __half *p_win16, *p_qkvw16, *p_outw16, *p_ff1w16, *p_ff2w16;
    cudaGetSymbolAddress((void**)&p_h, g_h);
    cudaGetSymbolAddress((void**)&p_sa, g_sa);
    cudaGetSymbolAddress((void**)&p_x16, g_x16);
    cudaGetSymbolAddress((void**)&p_h16, g_h16);
    cudaGetSymbolAddress((void**)&p_qkv16, g_qkv16);
    cudaGetSymbolAddress((void**)&p_ctx16, g_ctx16);
    cudaGetSymbolAddress((void**)&p_ff16, g_ff16);
    cudaGetSymbolAddress((void**)&p_win16, g_win16);
    cudaGetSymbolAddress((void**)&p_qkvw16, g_qkvw16);
    cudaGetSymbolAddress((void**)&p_outw16, g_outw16);
    cudaGetSymbolAddress((void**)&p_ff1w16, g_ff1w16);
    cudaGetSymbolAddress((void**)&p_ff2w16, g_ff2w16);

    pe_kernel<<<(SEQ * DMODEL + 255) / 256, 256>>>();

    conv(x, p_x16, NTOK * IN_DIM);
    conv(W_in, p_win16, DMODEL * IN_DIM);
    conv(qkv_w, p_qkvw16, NLAYER * 3 * DMODEL * DMODEL);
    conv(out_w, p_outw16, NLAYER * DMODEL * DMODEL);
    conv(ff1_w, p_ff1w16, NLAYER * FFDIM * DMODEL);
    conv(ff2_w, p_ff2w16, NLAYER * DMODEL * FFDIM);

    // input projection + PE: h (fp32 + fp16)
    {
        dim3 grid(DMODEL / 128, NTOK / 128);
        hgemm<2><<<grid, 256>>>(p_x16, p_win16, b_in, p_h, p_h16, NTOK, DMODEL, IN_DIM);
    }

    for (int l = 0; l < NLAYER; l++) {
        // qkv -> fp16
        {
            dim3 grid(3 * DMODEL / 128, NTOK / 128);
            hgemm<3><<<grid, 256>>>(p_h16, p_qkvw16 + (size_t)l * 3 * DMODEL * DMODEL,
                                    qkv_b + (size_t)l * 3 * DMODEL, nullptr, p_qkv16,
                                    NTOK, 3 * DMODEL, DMODEL);
        }
        // tensor-core flash attention -> ctx fp16
        {
            dim3 grid(BATCH * NHEAD, SEQ / 64);
            flash_mma<<<grid, 128>>>(p_qkv16, p_ctx16);
        }
        // out projection -> sa fp32
        {
            dim3 grid(DMODEL / 128, NTOK / 128);
            hgemm<0><<<grid, 256>>>(p_ctx16, p_outw16 + (size_t)l * DMODEL * DMODEL,
                                    out_b + (size_t)l * DMODEL, p_sa, nullptr,
                                    NTOK, DMODEL, DMODEL);
        }
        ln_kernel<<<NTOK, 256>>>(p_sa, ln1_w + (size_t)l * DMODEL, ln1_b + (size_t)l * DMODEL);
        // ff1 (relu) -> fp16
        {
            dim3 grid(FFDIM / 128, NTOK / 128);
            hgemm<1><<<grid, 256>>>(p_h16, p_ff1w16 + (size_t)l * FFDIM * DMODEL,
                                    ff1_b + (size_t)l * FFDIM, nullptr, p_ff16,
                                    NTOK, FFDIM, DMODEL);
        }
        // ff2 -> sa fp32
        {
            dim3 grid(DMODEL / 128, NTOK / 128);
            hgemm<0><<<grid, 256>>>(p_ff16, p_ff2w16 + (size_t)l * DMODEL * FFDIM,
                                    ff2_b + (size_t)l * DMODEL, p_sa, nullptr,
                                    NTOK, DMODEL, FFDIM);
        }
        ln_kernel<<<NTOK, 256>>>(p_sa, ln2_w + (size_t)l * DMODEL, ln2_b + (size_t)l * DMODEL);
    }

    final_kernel<<<BATCH, IN_DIM>>>(W_fc, b_fc, out);
}